// round 17
// baseline (speedup 1.0000x reference)
#include <cuda_runtime.h>
#include <math.h>

#define NN 80
#define PAIRS (NN * NN)          // 6400
#define MAX_ITERS 60
#define TOL 1e-3f
#define TPB 256

__global__ __launch_bounds__(TPB, 5)
void power_iter_kernel(const float* __restrict__ r_zeros,
                       const float* __restrict__ r_const,
                       const float* __restrict__ t_paths,
                       const float* __restrict__ weights_t,
                       const float* __restrict__ weights_r,
                       float* __restrict__ out) {
    __shared__ float wbuf[2][NN];  // ping-pong: unnormalized w = A v
    __shared__ float red_ww[8];    // per-warp partials of w.w
    __shared__ float red_vw[8];    // per-warp partials of v.(Av)
    __shared__ float s_n2;         // broadcast: ||w_out||^2
    __shared__ float s_ev;         // broadcast: v_in . (A v_in)

    const int p    = blockIdx.x;
    const int tid  = threadIdx.x;
    const int warp = tid >> 5;
    const int lane = tid & 31;
    const bool hi  = (lane & 16) != 0;
    const float C0 = 0.11180339887498949f;  // 1/sqrt(80)

    // ---- Build A = weights_r*r_zeros + r_const into registers, FUSED with
    // mv#0 (w0 = A v0 = C0*rowsum(A)) per row-pair to minimize live regs.
    // Warp w owns rows {w, w+8, ..., w+72} (reg r <-> row w+8r). Cols 0..63:
    // lane holds (lane, lane+32). Tail cols 64..79 packed: a2p[k] = tails of
    // pair (reg 2k: lanes 0-15, reg 2k+1: lanes 16-31). Coalesced, __ldcs.
    const size_t base = (size_t)p * (NN * NN);
    const float* __restrict__ rz = r_zeros   + base;
    const float* __restrict__ rc = r_const   + base;
    const float* __restrict__ wr = weights_r + base;

    float a0[10], a1[10], a2p[5];
    {
        float ww = 0.0f, vwacc = 0.0f;
        #pragma unroll
        for (int k = 0; k < 5; ++k) {
            const int rA = warp + (k << 4);      // row of reg 2k
            const int rB = rA + 8;               // row of reg 2k+1
            const int oA = rA * NN + lane;
            const int oB = rB * NN + lane;
            a0[2*k]   = fmaf(__ldcs(wr + oA),      __ldcs(rz + oA),      __ldcs(rc + oA));
            a1[2*k]   = fmaf(__ldcs(wr + oA + 32), __ldcs(rz + oA + 32), __ldcs(rc + oA + 32));
            a0[2*k+1] = fmaf(__ldcs(wr + oB),      __ldcs(rz + oB),      __ldcs(rc + oB));
            a1[2*k+1] = fmaf(__ldcs(wr + oB + 32), __ldcs(rz + oB + 32), __ldcs(rc + oB + 32));
            const int o2 = (hi ? rB : rA) * NN + 64 + (lane & 15);
            a2p[k] = fmaf(__ldcs(wr + o2), __ldcs(rz + o2), __ldcs(rc + o2));

            // inline mv#0 for this pair: rowsum fold
            float sA = a0[2*k]   + a1[2*k];
            float sB = a0[2*k+1] + a1[2*k+1];
            sA += __shfl_xor_sync(0xFFFFFFFFu, sA, 16);
            sB += __shfl_xor_sync(0xFFFFFFFFu, sB, 16);
            float u = (hi ? sB : sA) + a2p[k];
            u += __shfl_xor_sync(0xFFFFFFFFu, u, 8);
            u += __shfl_xor_sync(0xFFFFFFFFu, u, 4);
            u += __shfl_xor_sync(0xFFFFFFFFu, u, 2);
            u += __shfl_xor_sync(0xFFFFFFFFu, u, 1);
            u *= C0;                             // w0[row]
            if ((lane & 15) == 0) {
                wbuf[1][hi ? rB : rA] = u;
                ww    = fmaf(u, u, ww);
                vwacc = fmaf(C0, u, vwacc);      // v0[row] = C0
            }
        }
        ww    += __shfl_xor_sync(0xFFFFFFFFu, ww,    16);
        vwacc += __shfl_xor_sync(0xFFFFFFFFu, vwacc, 16);
        if (lane == 0) { red_ww[warp] = ww; red_vw[warp] = vwacc; }
        __syncthreads();
        if (tid == 0) {
            float A = 0.0f, B = 0.0f;
            #pragma unroll
            for (int k = 0; k < 8; ++k) { A += red_ww[k]; B += red_vw[k]; }
            s_n2 = A; s_ev = B;
        }
        __syncthreads();
    }

    // mv (QUAD-FOLD, R16-proven): rows in groups of 4 share last 3 stages.
    auto mv = [&](const float* in, float* outb, float inv) {
        const float vr0 = in[lane] * inv;
        const float vr1 = in[lane + 32] * inv;
        const float vt  = in[64 + (lane & 15)] * inv;
        float ww = 0.0f, vwacc = 0.0f;
        #pragma unroll
        for (int q = 0; q < 2; ++q) {
            const int r0 = 4*q;
            float s0 = fmaf(a1[r0],   vr1, a0[r0]   * vr0);
            float s1 = fmaf(a1[r0+1], vr1, a0[r0+1] * vr0);
            float s2 = fmaf(a1[r0+2], vr1, a0[r0+2] * vr0);
            float s3 = fmaf(a1[r0+3], vr1, a0[r0+3] * vr0);
            s0 += __shfl_xor_sync(0xFFFFFFFFu, s0, 16);
            s1 += __shfl_xor_sync(0xFFFFFFFFu, s1, 16);
            s2 += __shfl_xor_sync(0xFFFFFFFFu, s2, 16);
            s3 += __shfl_xor_sync(0xFFFFFFFFu, s3, 16);
            float uA = hi ? s1 : s0;            // lanes 0-15: r0, 16-31: r1
            uA = fmaf(a2p[2*q], vt, uA);
            float uB = hi ? s3 : s2;            // lanes 0-15: r2, 16-31: r3
            uB = fmaf(a2p[2*q+1], vt, uB);
            uA += __shfl_xor_sync(0xFFFFFFFFu, uA, 8);
            uB += __shfl_xor_sync(0xFFFFFFFFu, uB, 8);
            float u = (lane & 8) ? uB : uA;     // 8-groups: r0,r2,r1,r3
            u += __shfl_xor_sync(0xFFFFFFFFu, u, 4);
            u += __shfl_xor_sync(0xFFFFFFFFu, u, 2);
            u += __shfl_xor_sync(0xFFFFFFFFu, u, 1);
            if ((lane & 7) == 0) {
                const int ridx = 4*q + (((lane >> 3) & 1) << 1)
                                      + ((lane >> 4) & 1);
                const int row = warp + (ridx << 3);
                outb[row] = u;
                ww    = fmaf(u, u, ww);
                vwacc = fmaf(in[row] * inv, u, vwacc);
            }
        }
        {   // pair: regs 8,9 (rows w+64, w+72), tail a2p[4]
            float sA = fmaf(a1[8], vr1, a0[8] * vr0);
            float sB = fmaf(a1[9], vr1, a0[9] * vr0);
            sA += __shfl_xor_sync(0xFFFFFFFFu, sA, 16);
            sB += __shfl_xor_sync(0xFFFFFFFFu, sB, 16);
            float u = hi ? sB : sA;
            u = fmaf(a2p[4], vt, u);
            u += __shfl_xor_sync(0xFFFFFFFFu, u, 8);
            u += __shfl_xor_sync(0xFFFFFFFFu, u, 4);
            u += __shfl_xor_sync(0xFFFFFFFFu, u, 2);
            u += __shfl_xor_sync(0xFFFFFFFFu, u, 1);
            if ((lane & 15) == 0) {
                const int row = warp + ((hi ? 9 : 8) << 3);
                outb[row] = u;
                ww    = fmaf(u, u, ww);
                vwacc = fmaf(in[row] * inv, u, vwacc);
            }
        }
        ww    += __shfl_xor_sync(0xFFFFFFFFu, ww,    8);
        ww    += __shfl_xor_sync(0xFFFFFFFFu, ww,    16);
        vwacc += __shfl_xor_sync(0xFFFFFFFFu, vwacc, 8);
        vwacc += __shfl_xor_sync(0xFFFFFFFFu, vwacc, 16);
        if (lane == 0) { red_ww[warp] = ww; red_vw[warp] = vwacc; }
        __syncthreads();
        if (tid == 0) {
            float A = 0.0f, B = 0.0f;
            #pragma unroll
            for (int k = 0; k < 8; ++k) { A += red_ww[k]; B += red_vw[k]; }
            s_n2 = A; s_ev = B;
        }
        __syncthreads();
    };

    float ev = s_ev;   // ev0 = v0.(A v0)

    // ---- iterate: v_{k+1} = w_k/||w_k||; ev_{k+1} = v_{k+1}.(A v_{k+1})
    int bin = 1;
    float inv_last = 1.0f;
    for (int it = 0; it < MAX_ITERS; ++it) {
        const float inv = 1.0f / sqrtf(s_n2);     // uniform per-thread scalar
        mv(wbuf[bin], wbuf[bin ^ 1], inv);        // reads w*inv, writes A v_new
        inv_last = inv;
        const float ev_new = s_ev;
        if (fabsf(ev - ev_new) < TOL) break;      // v_final = wbuf[bin]*inv
        ev = ev_new;
        bin ^= 1;
    }

    // ---- out[i] += v_final[i] * (T[p] / v_final[src]),  src = p / n
    if (tid < NN) {
        const float tval = weights_t[p] * t_paths[p];
        const float coef = tval / (wbuf[bin][p / NN] * inv_last);
        atomicAdd(&out[tid], wbuf[bin][tid] * inv_last * coef);
    }
}

extern "C" void kernel_launch(void* const* d_in, const int* in_sizes, int n_in,
                              void* d_out, int out_size) {
    // metadata order: 0:x (unused), 1:r_zeros, 2:r_const, 3:t_paths,
    //                 4:weights_t, 5:weights_r
    const float* r_zeros   = (const float*)d_in[1];
    const float* r_const   = (const float*)d_in[2];
    const float* t_paths   = (const float*)d_in[3];
    const float* weights_t = (const float*)d_in[4];
    const float* weights_r = (const float*)d_in[5];
    float* out = (float*)d_out;

    // Graph-capturable memset node (replaces zero_out kernel launch).
    cudaMemsetAsync(out, 0, NN * sizeof(float));
    power_iter_kernel<<<PAIRS, TPB>>>(r_zeros, r_const, t_paths, weights_t,
                                      weights_r, out);
}